// round 5
// baseline (speedup 1.0000x reference)
#include <cuda_runtime.h>
#include <cuda_bf16.h>
#include <cstdint>

// Problem constants (match reference)
#define NUM_LEVELS   16
#define BASE_RES     16
#define N_POINTS     524288
#define N_ENTRIES    524309ull      // prime hashmap size
#define PS1          19349663ll     // second spatial-hash prime
#define START_HASH   6              // levels >= 6 use spatial hash
#define SMEM_LEVELS  3              // levels 0..2 cached in shared memory
#define SMEM_TAB_ENTRIES 5603       // sum of entries for levels 0..2 (float2 each)

#define TILE         32             // points per block-iteration
#define THREADS      512            // 16 warps: warp w <-> level w
#define NUM_TILES    (N_POINTS / TILE)   // 16384
#define STAGE_STRIDE 34             // floats per staged point row (32 + 2 pad, keeps 8B align)
#define STAGE_FLOATS (TILE * STAGE_STRIDE)   // per buffer
#define SMEM_BYTES   ((2 * SMEM_TAB_ENTRIES + 2 * STAGE_FLOATS) * 4)  // 44824 + 8704 = 53528

// Per-level base offsets into the table (cumulative entry counts)
__device__ __constant__ int LEVEL_OFF[NUM_LEVELS] = {
    0, 289, 1378, 5603, 22244, 88293, 351462,
    875771, 1400080, 1924389, 2448698, 2973007,
    3497316, 4021625, 4545934, 5070243
};

extern __shared__ float smem_raw[];

__global__ __launch_bounds__(THREADS)
void plane_encode_kernel(const float2* __restrict__ x,
                         const float2* __restrict__ tab,
                         float* __restrict__ out)
{
    float2* __restrict__ tab_s = (float2*)smem_raw;                 // levels 0..2
    float*  __restrict__ stage = smem_raw + 2 * SMEM_TAB_ENTRIES;   // [2][TILE][STAGE_STRIDE]

    const int tid = threadIdx.x;

    // One-time fill of the low-level tables (coalesced; amortized over ~37 tiles/block)
    for (int i = tid; i < SMEM_TAB_ENTRIES; i += THREADS)
        tab_s[i] = __ldg(&tab[i]);
    __syncthreads();

    // Compute mapping: warp = level (uniform per warp), lane = point-in-tile
    const int w    = tid >> 5;
    const int lane = tid & 31;
    const int   res   = BASE_RES << w;
    const float scale = (float)res;
    const int   S     = res + 1;
    const int   base  = LEVEL_OFF[w];

    // Store mapping: thread t writes (point = t>>4, level-pair float2 = t&15)
    const int op = tid >> 4;
    const int ol = tid & 15;

    int buf = 0;
    for (int tile = blockIdx.x; tile < NUM_TILES; tile += gridDim.x) {
        const int n = tile * TILE + lane;

        // All 16 warps read the same 32 float2s -> first warp misses, rest hit L1.
        const float2 xv = __ldg(&x[n]);

        const float fx0 = xv.x * scale;
        const float fx1 = xv.y * scale;

        // Corner integer coords — replicate reference: trunc(fx + corner) in fp32
        const int i0a = (int)fx0;
        const int i0b = (int)(fx0 + 1.0f);
        const int i1a = (int)fx1;
        const int i1b = (int)(fx1 + 1.0f);

        const float f0 = fx0 - (float)i0a;
        const float f1 = fx1 - (float)i1a;
        const float g0 = 1.0f - f0;
        const float g1 = 1.0f - f1;
        const float w00 = g0 * g1;
        const float w01 = g0 * f1;
        const float w10 = f0 * g1;
        const float w11 = f0 * f1;

        float2 v00, v01, v10, v11;
        if (w < SMEM_LEVELS) {
            // tiny dense levels: shared memory (conflict degree ~2-4 << LDG wavefronts)
            v00 = tab_s[base + i0a * S + i1a];
            v01 = tab_s[base + i0a * S + i1b];
            v10 = tab_s[base + i0b * S + i1a];
            v11 = tab_s[base + i0b * S + i1b];
        } else if (w < START_HASH) {
            // mid dense levels: default caching — these now live in un-thrashed L1
            v00 = __ldg(&tab[base + i0a * S + i1a]);
            v01 = __ldg(&tab[base + i0a * S + i1b]);
            v10 = __ldg(&tab[base + i0b * S + i1a]);
            v11 = __ldg(&tab[base + i0b * S + i1b]);
        } else {
            // hashed levels: compulsory random 32B sectors — L2-only, don't thrash L1
            const unsigned long long ha = (unsigned long long)((long long)i1a * PS1);
            const unsigned long long hb = (unsigned long long)((long long)i1b * PS1);
            const unsigned long long a0 = (unsigned long long)(long long)i0a;
            const unsigned long long b0 = (unsigned long long)(long long)i0b;
            const int j00 = (int)(unsigned)((a0 ^ ha) % N_ENTRIES);
            const int j01 = (int)(unsigned)((a0 ^ hb) % N_ENTRIES);
            const int j10 = (int)(unsigned)((b0 ^ ha) % N_ENTRIES);
            const int j11 = (int)(unsigned)((b0 ^ hb) % N_ENTRIES);
            v00 = __ldcg(&tab[base + j00]);
            v01 = __ldcg(&tab[base + j01]);
            v10 = __ldcg(&tab[base + j10]);
            v11 = __ldcg(&tab[base + j11]);
        }

        float2 r;
        r.x = w00 * v00.x + w01 * v01.x + w10 * v10.x + w11 * v11.x;
        r.y = w00 * v00.y + w01 * v01.y + w10 * v10.y + w11 * v11.y;

        // Transpose through smem: stage[buf][lane][2*w] = r  (stride 34 -> 2-way conflicts max)
        *(float2*)&stage[buf * STAGE_FLOATS + lane * STAGE_STRIDE + 2 * w] = r;
        __syncthreads();

        // Coalesced 128B-per-point rows, streaming (don't evict the table from L2)
        const float2 o = *(const float2*)&stage[buf * STAGE_FLOATS + op * STAGE_STRIDE + 2 * ol];
        __stcs((float2*)(out + (size_t)(tile * TILE + op) * (NUM_LEVELS * 2)) + ol, o);

        // Double buffer: next iter writes the other buffer; WAR on this buffer is
        // protected by the barrier inside the NEXT iteration (program order:
        // this LDS -> next STS -> next BAR -> iter+2 STS to this buffer).
        buf ^= 1;
    }
}

extern "C" void kernel_launch(void* const* d_in, const int* in_sizes, int n_in,
                              void* d_out, int out_size)
{
    const float2* x    = (const float2*)d_in[0];
    const float2* data = (const float2*)d_in[1];
    float*        out  = (float*)d_out;

    static bool attr_set = false;
    if (!attr_set) {
        cudaFuncSetAttribute(plane_encode_kernel,
                             cudaFuncAttributeMaxDynamicSharedMemorySize, SMEM_BYTES);
        attr_set = true;
    }

    // Persistent-style grid: ~3 blocks/SM (smem 53.5KB each), grid-stride over 16384 tiles
    const int blocks = 148 * 3;
    plane_encode_kernel<<<blocks, THREADS, SMEM_BYTES>>>(x, data, out);
}

// round 6
// speedup vs baseline: 2.2017x; 2.2017x over previous
#include <cuda_runtime.h>
#include <cuda_bf16.h>
#include <cstdint>

// Problem constants (match reference)
#define NUM_LEVELS   16
#define BASE_RES     16
#define N_POINTS     524288
#define N_ENTRIES    524309ull      // prime hashmap size
#define PS1          19349663ll     // second spatial-hash prime
#define START_HASH   6              // levels >= 6 use spatial hash
#define SMEM_LEVELS  3              // levels 0..2 served from shared memory
#define SMEM_TAB_ENTRIES 5603       // total float2 entries for levels 0..2
#define SMEM_BYTES   (SMEM_TAB_ENTRIES * 8)   // 44824 B

#define THREADS      512
#define BLOCKS       (148 * 2)      // persistent; 2 blocks/SM -> 89.6KB smem, ~138KB L1 left

// Per-level base offsets into the table (cumulative entry counts)
__device__ __constant__ int LEVEL_OFF[NUM_LEVELS] = {
    0, 289, 1378, 5603, 22244, 88293, 351462,
    875771, 1400080, 1924389, 2448698, 2973007,
    3497316, 4021625, 4545934, 5070243
};

extern __shared__ float2 tab_s[];   // levels 0..2 (5603 float2)

__global__ __launch_bounds__(THREADS)
void plane_encode_kernel(const float2* __restrict__ x,
                         const float2* __restrict__ tab,
                         float* __restrict__ out)
{
    const int tid = threadIdx.x;

    // One-time fill of the low-level tables (coalesced, once per block lifetime)
    for (int i = tid; i < SMEM_TAB_ENTRIES; i += THREADS)
        tab_s[i] = __ldg(&tab[i]);
    __syncthreads();   // only barrier in the kernel

    // Work-item mapping: t = n*16 + l.  stride is a multiple of 16, so the
    // level l is loop-invariant per thread -> all per-level constants hoist.
    const int t0 = blockIdx.x * THREADS + tid;
    const int l  = t0 & 15;
    int       n  = t0 >> 4;
    const int n_stride = (BLOCKS * THREADS) >> 4;   // points per grid stride

    const int   res   = BASE_RES << l;
    const float scale = (float)res;
    const int   S     = res + 1;
    const int   base  = LEVEL_OFF[l];

    for (; n < N_POINTS; n += n_stride) {
        // 16 consecutive lanes share one point's coords: L1-broadcast load.
        const float2 xv = __ldg(&x[n]);

        const float fx0 = xv.x * scale;
        const float fx1 = xv.y * scale;

        // Corner integer coords — replicate reference: trunc(fx + corner) in fp32
        const int i0a = (int)fx0;
        const int i0b = (int)(fx0 + 1.0f);
        const int i1a = (int)fx1;
        const int i1b = (int)(fx1 + 1.0f);

        const float f0 = fx0 - (float)i0a;
        const float f1 = fx1 - (float)i1a;
        const float g0 = 1.0f - f0;
        const float g1 = 1.0f - f1;
        const float w00 = g0 * g1;
        const float w01 = g0 * f1;
        const float w10 = f0 * g1;
        const float w11 = f0 * f1;

        float2 v00, v01, v10, v11;
        if (l >= START_HASH) {
            // hashed levels: compulsory random 32B sectors — L2-only (don't thrash L1)
            const unsigned long long ha = (unsigned long long)((long long)i1a * PS1);
            const unsigned long long hb = (unsigned long long)((long long)i1b * PS1);
            const unsigned long long a0 = (unsigned long long)(long long)i0a;
            const unsigned long long b0 = (unsigned long long)(long long)i0b;
            const int j00 = (int)(unsigned)((a0 ^ ha) % N_ENTRIES);
            const int j01 = (int)(unsigned)((a0 ^ hb) % N_ENTRIES);
            const int j10 = (int)(unsigned)((b0 ^ ha) % N_ENTRIES);
            const int j11 = (int)(unsigned)((b0 ^ hb) % N_ENTRIES);
            v00 = __ldcg(&tab[base + j00]);
            v01 = __ldcg(&tab[base + j01]);
            v10 = __ldcg(&tab[base + j10]);
            v11 = __ldcg(&tab[base + j11]);
        } else if (l < SMEM_LEVELS) {
            // tiny dense levels from shared memory: 1-2 phases instead of
            // multi-line LDG replays
            v00 = tab_s[base + i0a * S + i1a];
            v01 = tab_s[base + i0a * S + i1b];
            v10 = tab_s[base + i0b * S + i1a];
            v11 = tab_s[base + i0b * S + i1b];
        } else {
            // mid dense levels (34KB / 528KB / 2.1MB): L1-cached, now un-thrashed
            v00 = __ldg(&tab[base + i0a * S + i1a]);
            v01 = __ldg(&tab[base + i0a * S + i1b]);
            v10 = __ldg(&tab[base + i0b * S + i1a]);
            v11 = __ldg(&tab[base + i0b * S + i1b]);
        }

        float2 r;
        r.x = w00 * v00.x + w01 * v01.x + w10 * v10.x + w11 * v11.x;
        r.y = w00 * v00.y + w01 * v01.y + w10 * v10.y + w11 * v11.y;

        // 16 lanes of one point write its contiguous 128B output row; streaming
        // store keeps the 67MB output from evicting the table in L2.
        __stcs((float2*)(out + (size_t)n * (NUM_LEVELS * 2)) + l, r);
    }
}

extern "C" void kernel_launch(void* const* d_in, const int* in_sizes, int n_in,
                              void* d_out, int out_size)
{
    const float2* x    = (const float2*)d_in[0];
    const float2* data = (const float2*)d_in[1];
    float*        out  = (float*)d_out;

    static bool attr_set = false;
    if (!attr_set) {
        cudaFuncSetAttribute(plane_encode_kernel,
                             cudaFuncAttributeMaxDynamicSharedMemorySize, SMEM_BYTES);
        attr_set = true;
    }

    plane_encode_kernel<<<BLOCKS, THREADS, SMEM_BYTES>>>(x, data, out);
}

// round 7
// speedup vs baseline: 2.3069x; 1.0478x over previous
#include <cuda_runtime.h>
#include <cuda_bf16.h>
#include <cstdint>

// Problem constants (match reference)
#define NUM_LEVELS   16
#define BASE_RES     16
#define N_POINTS     524288
#define N_ENTRIES    524309ull      // prime hashmap size
#define PS1          19349663ll     // second spatial-hash prime
#define START_HASH   6              // levels >= 6 use spatial hash
#define SMEM_LEVELS  3              // levels 0..2 served from shared memory
#define SMEM_TAB_ENTRIES 5603       // total float2 entries for levels 0..2
#define SMEM_BYTES   (SMEM_TAB_ENTRIES * 8)   // 44824 B

#define THREADS      512
#define BLOCKS       (148 * 4)      // 4 blocks/SM: 179.2KB smem/SM, 64 warps/SM = FULL occ

// Per-level base offsets into the table (cumulative entry counts)
__device__ __constant__ int LEVEL_OFF[NUM_LEVELS] = {
    0, 289, 1378, 5603, 22244, 88293, 351462,
    875771, 1400080, 1924389, 2448698, 2973007,
    3497316, 4021625, 4545934, 5070243
};

extern __shared__ float2 tab_s[];   // levels 0..2 (5603 float2)

__global__ __launch_bounds__(THREADS)
void plane_encode_kernel(const float2* __restrict__ x,
                         const float2* __restrict__ tab,
                         float* __restrict__ out)
{
    const int tid = threadIdx.x;

    // One-time fill of the low-level tables (coalesced, once per block lifetime;
    // 592 blocks x 44.8KB = 26MB of L2 reads, amortized over ~28 iterations)
    for (int i = tid; i < SMEM_TAB_ENTRIES; i += THREADS)
        tab_s[i] = __ldg(&tab[i]);
    __syncthreads();   // only barrier in the kernel

    // Work-item mapping: t = n*16 + l.  Grid stride is a multiple of 16, so the
    // level l is loop-invariant per thread -> all per-level constants hoist.
    const int t0 = blockIdx.x * THREADS + tid;
    const int l  = t0 & 15;
    int       n  = t0 >> 4;
    const int n_stride = (BLOCKS * THREADS) >> 4;   // 18944 points per stride

    const int   res   = BASE_RES << l;
    const float scale = (float)res;
    const int   S     = res + 1;
    const int   base  = LEVEL_OFF[l];

    for (; n < N_POINTS; n += n_stride) {
        // 16 consecutive lanes share one point's coords: L1-broadcast load.
        const float2 xv = __ldg(&x[n]);

        const float fx0 = xv.x * scale;
        const float fx1 = xv.y * scale;

        // Corner integer coords — replicate reference: trunc(fx + corner) in fp32
        const int i0a = (int)fx0;
        const int i0b = (int)(fx0 + 1.0f);
        const int i1a = (int)fx1;
        const int i1b = (int)(fx1 + 1.0f);

        const float f0 = fx0 - (float)i0a;
        const float f1 = fx1 - (float)i1a;
        const float g0 = 1.0f - f0;
        const float g1 = 1.0f - f1;
        const float w00 = g0 * g1;
        const float w01 = g0 * f1;
        const float w10 = f0 * g1;
        const float w11 = f0 * f1;

        float2 v00, v01, v10, v11;
        if (l >= START_HASH) {
            // hashed levels: compulsory random 32B sectors — L2-only (keep L1 clean)
            const unsigned long long ha = (unsigned long long)((long long)i1a * PS1);
            const unsigned long long hb = (unsigned long long)((long long)i1b * PS1);
            const unsigned long long a0 = (unsigned long long)(long long)i0a;
            const unsigned long long b0 = (unsigned long long)(long long)i0b;
            const int j00 = (int)(unsigned)((a0 ^ ha) % N_ENTRIES);
            const int j01 = (int)(unsigned)((a0 ^ hb) % N_ENTRIES);
            const int j10 = (int)(unsigned)((b0 ^ ha) % N_ENTRIES);
            const int j11 = (int)(unsigned)((b0 ^ hb) % N_ENTRIES);
            v00 = __ldcg(&tab[base + j00]);
            v01 = __ldcg(&tab[base + j01]);
            v10 = __ldcg(&tab[base + j10]);
            v11 = __ldcg(&tab[base + j11]);
        } else if (l < SMEM_LEVELS) {
            // tiny dense levels from shared memory: ~3-4 conflict phases per LDS
            // instead of ~30 L1 wavefronts per LDG — direct relief on the binding pipe
            v00 = tab_s[base + i0a * S + i1a];
            v01 = tab_s[base + i0a * S + i1b];
            v10 = tab_s[base + i0b * S + i1a];
            v11 = tab_s[base + i0b * S + i1b];
        } else if (l == 3) {
            // 133KB level: partial L1 hits in the ~49KB carveout
            v00 = __ldg(&tab[base + i0a * S + i1a]);
            v01 = __ldg(&tab[base + i0a * S + i1b]);
            v10 = __ldg(&tab[base + i0b * S + i1a]);
            v11 = __ldg(&tab[base + i0b * S + i1b]);
        } else {
            // 528KB / 2.1MB levels: can't live in 49KB L1 — don't pollute it
            v00 = __ldcg(&tab[base + i0a * S + i1a]);
            v01 = __ldcg(&tab[base + i0a * S + i1b]);
            v10 = __ldcg(&tab[base + i0b * S + i1a]);
            v11 = __ldcg(&tab[base + i0b * S + i1b]);
        }

        float2 r;
        r.x = w00 * v00.x + w01 * v01.x + w10 * v10.x + w11 * v11.x;
        r.y = w00 * v00.y + w01 * v01.y + w10 * v10.y + w11 * v11.y;

        // 16 lanes of one point write its contiguous 128B output row; streaming
        // store keeps the 67MB output from evicting the table in L2.
        __stcs((float2*)(out + (size_t)n * (NUM_LEVELS * 2)) + l, r);
    }
}

extern "C" void kernel_launch(void* const* d_in, const int* in_sizes, int n_in,
                              void* d_out, int out_size)
{
    const float2* x    = (const float2*)d_in[0];
    const float2* data = (const float2*)d_in[1];
    float*        out  = (float*)d_out;

    static bool attr_set = false;
    if (!attr_set) {
        cudaFuncSetAttribute(plane_encode_kernel,
                             cudaFuncAttributeMaxDynamicSharedMemorySize, SMEM_BYTES);
        attr_set = true;
    }

    plane_encode_kernel<<<BLOCKS, THREADS, SMEM_BYTES>>>(x, data, out);
}

// round 8
// speedup vs baseline: 2.5216x; 1.0931x over previous
#include <cuda_runtime.h>
#include <cuda_bf16.h>
#include <cstdint>

// Problem constants (match reference)
#define NUM_LEVELS   16
#define BASE_RES     16
#define N_POINTS     524288
#define N_ENTRIES    524309ull      // prime hashmap size
#define PS1          19349663ll     // second spatial-hash prime
#define START_HASH   6              // levels >= 6 use spatial hash

#define THREADS      256
#define HASH_ITEMS   (N_POINTS * 10)   // levels 6..15
#define DENSE_ITEMS  (N_POINTS * 6)    // levels 0..5
#define HASH_BLOCKS  (HASH_ITEMS / THREADS)    // 20480
#define DENSE_BLOCKS (DENSE_ITEMS / THREADS)   // 12288
#define TOTAL_BLOCKS (HASH_BLOCKS + DENSE_BLOCKS)  // 32768 (5:3 ratio, exact)

// Per-level base offsets into the table (cumulative entry counts)
__device__ __constant__ int LEVEL_OFF[NUM_LEVELS] = {
    0, 289, 1378, 5603, 22244, 88293, 351462,
    875771, 1400080, 1924389, 2448698, 2973007,
    3497316, 4021625, 4545934, 5070243
};

__global__ __launch_bounds__(THREADS)
void plane_encode_kernel(const float2* __restrict__ x,
                         const float2* __restrict__ tab,
                         float* __restrict__ out)
{
    // Block specialization in a 5:3 interleave so both traffic classes
    // (L2-bound hash, L1-bound dense) are live on every SM at all times.
    const int b   = blockIdx.x;
    const int pos = b & 7;
    const bool is_hash = (pos < 5);

    if (is_hash) {
        // ---- hash blocks: levels 6..15, fully uniform warps ----
        const int hb   = (b >> 3) * 5 + pos;
        const int item = hb * THREADS + threadIdx.x;     // item = n*10 + j
        const int n    = item / 10;                      // magic-mul div
        const int j    = item - n * 10;
        const int l    = j + START_HASH;

        const float2 xv = __ldg(&x[n]);                  // mostly broadcast in-warp

        const float scale = (float)(BASE_RES << l);
        const float fx0 = xv.x * scale;
        const float fx1 = xv.y * scale;

        const int i0a = (int)fx0;
        const int i0b = (int)(fx0 + 1.0f);
        const int i1a = (int)fx1;
        const int i1b = (int)(fx1 + 1.0f);

        const float f0 = fx0 - (float)i0a;
        const float f1 = fx1 - (float)i1a;
        const float g0 = 1.0f - f0;
        const float g1 = 1.0f - f1;

        // spatial hash: (ix0 ^ (ix1 * PS1)) % N_ENTRIES (64-bit, then mod prime)
        const unsigned long long ha = (unsigned long long)((long long)i1a * PS1);
        const unsigned long long hb64 = (unsigned long long)((long long)i1b * PS1);
        const unsigned long long a0 = (unsigned long long)(long long)i0a;
        const unsigned long long b0 = (unsigned long long)(long long)i0b;
        const int j00 = (int)(unsigned)((a0 ^ ha)   % N_ENTRIES);
        const int j01 = (int)(unsigned)((a0 ^ hb64) % N_ENTRIES);
        const int j10 = (int)(unsigned)((b0 ^ ha)   % N_ENTRIES);
        const int j11 = (int)(unsigned)((b0 ^ hb64) % N_ENTRIES);

        const int base = LEVEL_OFF[l];
        // compulsory random 32B sectors: L2-only, keep L1 clean for dense blocks
        const float2 v00 = __ldcg(&tab[base + j00]);
        const float2 v01 = __ldcg(&tab[base + j01]);
        const float2 v10 = __ldcg(&tab[base + j10]);
        const float2 v11 = __ldcg(&tab[base + j11]);

        const float w00 = g0 * g1, w01 = g0 * f1, w10 = f0 * g1, w11 = f0 * f1;
        float2 r;
        r.x = w00 * v00.x + w01 * v01.x + w10 * v10.x + w11 * v11.x;
        r.y = w00 * v00.y + w01 * v01.y + w10 * v10.y + w11 * v11.y;

        // consecutive items -> consecutive 8B slots (floats 12..31 of row n)
        __stcs((float2*)(out + (size_t)n * (NUM_LEVELS * 2)) + l, r);
    } else {
        // ---- dense blocks: levels 0..5, fully uniform warps ----
        const int db   = (b >> 3) * 3 + (pos - 5);
        const int item = db * THREADS + threadIdx.x;     // item = n*6 + j
        const int n    = item / 6;
        const int l    = item - n * 6;

        const float2 xv = __ldg(&x[n]);

        const int   res   = BASE_RES << l;
        const float scale = (float)res;
        const float fx0 = xv.x * scale;
        const float fx1 = xv.y * scale;

        const int i0a = (int)fx0;
        const int i0b = (int)(fx0 + 1.0f);
        const int i1a = (int)fx1;
        const int i1b = (int)(fx1 + 1.0f);

        const float f0 = fx0 - (float)i0a;
        const float f1 = fx1 - (float)i1a;
        const float g0 = 1.0f - f0;
        const float g1 = 1.0f - f1;

        const int S = res + 1;
        const int base = LEVEL_OFF[l];
        // small dense tables: L1-cached gathers (levels 0..3 fit the 228KB carveout)
        const float2 v00 = __ldg(&tab[base + i0a * S + i1a]);
        const float2 v01 = __ldg(&tab[base + i0a * S + i1b]);
        const float2 v10 = __ldg(&tab[base + i0b * S + i1a]);
        const float2 v11 = __ldg(&tab[base + i0b * S + i1b]);

        const float w00 = g0 * g1, w01 = g0 * f1, w10 = f0 * g1, w11 = f0 * f1;
        float2 r;
        r.x = w00 * v00.x + w01 * v01.x + w10 * v10.x + w11 * v11.x;
        r.y = w00 * v00.y + w01 * v01.y + w10 * v10.y + w11 * v11.y;

        // consecutive items -> consecutive 8B slots (floats 0..11 of row n)
        __stcs((float2*)(out + (size_t)n * (NUM_LEVELS * 2)) + l, r);
    }
}

extern "C" void kernel_launch(void* const* d_in, const int* in_sizes, int n_in,
                              void* d_out, int out_size)
{
    const float2* x    = (const float2*)d_in[0];
    const float2* data = (const float2*)d_in[1];
    float*        out  = (float*)d_out;

    plane_encode_kernel<<<TOTAL_BLOCKS, THREADS>>>(x, data, out);
}